// round 4
// baseline (speedup 1.0000x reference)
#include <cuda_runtime.h>
#include <cuda_bf16.h>
#include <cstdint>

#define Bdim 16
#define Ndim 2048
#define Ddim 1024
#define Pdim 2048

// ---------------- device scratch (static; allocation-free rule) ----------------
__device__ __align__(256) int8_t g_x0[(size_t)Bdim * Ndim * Ddim];   // x limb0 [b][n][d]
__device__ __align__(256) int8_t g_x1[(size_t)Bdim * Ndim * Ddim];   // x limb1
__device__ __align__(256) int8_t g_p0[(size_t)Pdim * Ddim];          // proto limb0 [p][d]
__device__ __align__(256) int8_t g_p1[(size_t)Pdim * Ddim];
__device__ __align__(256) int8_t g_pt0[(size_t)Ddim * Pdim];         // protoT limb0 [d][p]
__device__ __align__(256) int8_t g_pt1[(size_t)Ddim * Pdim];
__device__ __align__(256) float  g_ZT[(size_t)Bdim * Ndim * Pdim];   // Z^T [b][n][p]
__device__ __align__(256) int8_t g_a0[(size_t)Bdim * Ndim * Pdim];   // exp limb0 [b][n][p]
__device__ __align__(256) int8_t g_a1[(size_t)Bdim * Ndim * Pdim];   // exp limb1
__device__ __align__(256) float  g_sx[(size_t)Bdim * Ndim];          // x row scale (limb0 mult)
__device__ __align__(256) float  g_inv[(size_t)Bdim * Ndim];         // 1/sum_exp

// ---------------- baseline-PTX helpers (sm_80-class only) ----------------------
__device__ __forceinline__ uint32_t smem_u32_of(const void* p) {
    uint32_t a;
    asm("{ .reg .u64 t; cvta.to.shared.u64 t, %1; cvt.u32.u64 %0, t; }" : "=r"(a) : "l"(p));
    return a;
}
__device__ __forceinline__ void cpasync16(uint32_t s, const void* g) {
    asm volatile("cp.async.cg.shared.global [%0], [%1], 16;" :: "r"(s), "l"(g));
}
#define CP_COMMIT() asm volatile("cp.async.commit_group;")
#define CP_WAIT(n)  asm volatile("cp.async.wait_group %0;" :: "n"(n))

__device__ __forceinline__ void ldsm4(uint32_t* r, uint32_t addr) {
    asm volatile("ldmatrix.sync.aligned.m8n8.x4.shared.b16 {%0,%1,%2,%3}, [%4];"
                 : "=r"(r[0]), "=r"(r[1]), "=r"(r[2]), "=r"(r[3]) : "r"(addr));
}
// s8 x s8 -> s32, m16n8k32. Byte layout of frags identical to bf16 m16n8k16.
__device__ __forceinline__ void mma16832(int* c, const uint32_t* a, const uint32_t* b) {
    asm volatile("mma.sync.aligned.m16n8k32.row.col.s32.s8.s8.s32 "
                 "{%0,%1,%2,%3}, {%4,%5,%6,%7}, {%8,%9}, {%0,%1,%2,%3};"
                 : "+r"(c[0]), "+r"(c[1]), "+r"(c[2]), "+r"(c[3])
                 : "r"(a[0]), "r"(a[1]), "r"(a[2]), "r"(a[3]), "r"(b[0]), "r"(b[1]));
}

// ---------------- tiling constants ----------------
static constexpr int KTB = 128;               // k bytes (=int8 elems) per stage
static constexpr int ROWB = 144;              // padded smem row bytes (128 + 16)
static constexpr int TILE_B = 128 * ROWB;     // 18432
static constexpr int STAGE_B = 4 * TILE_B;    // A0 A1 B0 B1 = 73728
static constexpr int DYN_SMEM = 2 * STAGE_B;  // 147456

// load one stage (4 tiles x 128 rows x 128B) via 16 cp.async per thread
__device__ __forceinline__ void load_stage(
    const int8_t* gA0, const int8_t* gA1,
    const int8_t* gB0, const int8_t* gB1,
    size_t Ks, int k0, uint32_t sbase, int tid)
{
    const int8_t* G[4] = {gA0, gA1, gB0, gB1};
#pragma unroll
    for (int j = 0; j < 16; j++) {
        const int idx = tid + j * 256;        // 0..4095
        const int tile = idx >> 10;           // compile-time-ish after unroll
        const int c = idx & 1023;
        const int row = c >> 3, q = c & 7;
        cpasync16(sbase + tile * TILE_B + row * ROWB + q * 16,
                  G[tile] + (size_t)row * Ks + k0 + q * 16);
    }
}

// one k128 stage: 4 k32-steps x (4 m-frags x 4 n-frags x 3 limb-MMAs)
__device__ __forceinline__ void compute_stage(
    uint32_t sbase, int wm, int wn, uint32_t aoff, uint32_t boff,
    int accH[4][4][4], int accL[4][4][4])
{
    const uint32_t sA0 = sbase;
    const uint32_t sA1 = sbase + TILE_B;
    const uint32_t sB0 = sbase + 2 * TILE_B;
    const uint32_t sB1 = sbase + 3 * TILE_B;
#pragma unroll
    for (int ks = 0; ks < 4; ks++) {
        const uint32_t kb = ks * 32;
        uint32_t b0[8], b1[8];
#pragma unroll
        for (int f = 0; f < 2; f++) {
            uint32_t off = (wn * 32 + f * 16) * ROWB + kb + boff;
            ldsm4(b0 + f * 4, sB0 + off);
            ldsm4(b1 + f * 4, sB1 + off);
        }
#pragma unroll
        for (int mf = 0; mf < 4; mf++) {
            uint32_t off = (wm * 64 + mf * 16) * ROWB + kb + aoff;
            uint32_t a0[4], a1[4];
            ldsm4(a0, sA0 + off);
            ldsm4(a1, sA1 + off);
#pragma unroll
            for (int nf = 0; nf < 4; nf++) {
                mma16832(accH[mf][nf], a0, b0 + nf * 2);
                mma16832(accL[mf][nf], a0, b1 + nf * 2);
                mma16832(accL[mf][nf], a1, b0 + nf * 2);
            }
        }
    }
}

__device__ __forceinline__ void gemm_mainloop(
    const int8_t* gA0, const int8_t* gA1,
    const int8_t* gB0, const int8_t* gB1,
    size_t Ks, int T, uint32_t smem_b, int tid,
    int accH[4][4][4], int accL[4][4][4])
{
    const int lane = tid & 31, wid = tid >> 5;
    const int wm = wid & 1, wn = wid >> 1;
    const uint32_t aoff = (uint32_t)((lane & 15) * ROWB + ((lane & 16) ? 16 : 0));
    const uint32_t boff = (uint32_t)(((lane & 7) + ((lane & 16) ? 8 : 0)) * ROWB
                                     + ((lane & 8) ? 16 : 0));
#pragma unroll
    for (int mf = 0; mf < 4; mf++)
#pragma unroll
        for (int nf = 0; nf < 4; nf++)
#pragma unroll
            for (int e = 0; e < 4; e++) { accH[mf][nf][e] = 0; accL[mf][nf][e] = 0; }

    load_stage(gA0, gA1, gB0, gB1, Ks, 0, smem_b, tid);
    CP_COMMIT();
    load_stage(gA0, gA1, gB0, gB1, Ks, KTB, smem_b + STAGE_B, tid);
    CP_COMMIT();

    for (int t = 0; t < T; t++) {
        if (t == T - 1) { CP_WAIT(0); } else { CP_WAIT(1); }
        __syncthreads();
        compute_stage(smem_b + (t & 1) * STAGE_B, wm, wn, aoff, boff, accH, accL);
        __syncthreads();
        if (t + 2 < T) {
            load_stage(gA0, gA1, gB0, gB1, Ks, (t + 2) * KTB, smem_b + (t & 1) * STAGE_B, tid);
            CP_COMMIT();
        }
    }
}

// ---------------------------------------------------------------------------
// quantizers: fp32 -> 2 int8 limbs
// ---------------------------------------------------------------------------
__global__ __launch_bounds__(256) void quant_x(const float* __restrict__ x) {
    const int w = blockIdx.x * 8 + (threadIdx.x >> 5);  // row 0..B*N-1
    const int lane = threadIdx.x & 31;
    const float4* row = (const float4*)(x + (size_t)w * Ddim);
    float4 v[8];
    float am = 0.f;
#pragma unroll
    for (int i = 0; i < 8; i++) {
        v[i] = row[lane + 32 * i];
        am = fmaxf(am, fmaxf(fmaxf(fabsf(v[i].x), fabsf(v[i].y)),
                             fmaxf(fabsf(v[i].z), fabsf(v[i].w))));
    }
#pragma unroll
    for (int o = 16; o > 0; o >>= 1) am = fmaxf(am, __shfl_xor_sync(0xFFFFFFFFu, am, o));
    const float inv = (am > 0.f) ? 127.f / am : 0.f;
#pragma unroll
    for (int i = 0; i < 8; i++) {
        float q0 = v[i].x * inv, q1 = v[i].y * inv, q2 = v[i].z * inv, q3 = v[i].w * inv;
        int i0 = __float2int_rn(q0), i1 = __float2int_rn(q1);
        int i2 = __float2int_rn(q2), i3 = __float2int_rn(q3);
        char4 c0 = {(char)i0, (char)i1, (char)i2, (char)i3};
        char4 c1 = {(char)__float2int_rn((q0 - i0) * 128.f),
                    (char)__float2int_rn((q1 - i1) * 128.f),
                    (char)__float2int_rn((q2 - i2) * 128.f),
                    (char)__float2int_rn((q3 - i3) * 128.f)};
        size_t off = (size_t)w * Ddim + (lane + 32 * i) * 4;
        *(char4*)(g_x0 + off) = c0;
        *(char4*)(g_x1 + off) = c1;
    }
    if (lane == 0) g_sx[w] = am * (1.f / 127.f);
}
__global__ __launch_bounds__(256) void quant_p(const float* __restrict__ proto) {
    int idx = blockIdx.x * 256 + threadIdx.x;
    int p = idx / Ddim, d = idx % Ddim;
    float q = proto[idx] * 127.f;
    int i0 = __float2int_rn(q);
    int i1 = __float2int_rn((q - i0) * 128.f);
    g_p0[idx] = (int8_t)i0; g_p1[idx] = (int8_t)i1;
    g_pt0[(size_t)d * Pdim + p] = (int8_t)i0;
    g_pt1[(size_t)d * Pdim + p] = (int8_t)i1;
}

// ---------------------------------------------------------------------------
// K1: Z^T[b][n][p] = x.proto^T + gumbel.  M=n(128), N=p(128), K=d(1024 bytes).
// ---------------------------------------------------------------------------
__global__ __launch_bounds__(256) void k1_logits(const float* __restrict__ u) {
    extern __shared__ char smem[];
    const uint32_t smem_b = smem_u32_of(smem);
    const int tid = threadIdx.x, lane = tid & 31, wid = tid >> 5;
    const int wm = wid & 1, wn = wid >> 1;
    const int bn = blockIdx.x, bp = blockIdx.y, b = blockIdx.z;

    int accH[4][4][4], accL[4][4][4];
    gemm_mainloop(g_x0 + ((size_t)b * Ndim + bn * 128) * Ddim,
                  g_x1 + ((size_t)b * Ndim + bn * 128) * Ddim,
                  g_p0 + (size_t)(bp * 128) * Ddim,
                  g_p1 + (size_t)(bp * 128) * Ddim,
                  (size_t)Ddim, Ddim / KTB, smem_b, tid, accH, accL);

    // stage u tile [p0..p0+127][n0..n0+127] into smem (stride 132 floats)
    __syncthreads();
    float* u_s = (float*)smem;
    const float* ug = u + ((size_t)b * Pdim + (size_t)bp * 128) * Ndim + bn * 128;
#pragma unroll
    for (int j = 0; j < 16; j++) {
        int idx = tid + j * 256;
        int row = idx >> 5, c4 = idx & 31;
        float4 v = *(const float4*)(ug + (size_t)row * Ndim + c4 * 4);
        *(float4*)(u_s + row * 132 + c4 * 4) = v;
    }
    __syncthreads();

    const int gID = lane >> 2, tg = lane & 3;
#pragma unroll
    for (int mf = 0; mf < 4; mf++) {
#pragma unroll
        for (int r2 = 0; r2 < 2; r2++) {
            const int nl = wm * 64 + mf * 16 + gID + r2 * 8;
            const float sc = g_sx[(size_t)b * Ndim + bn * 128 + nl] * (1.f / 127.f);
            const size_t rowbase = ((size_t)b * Ndim + bn * 128 + nl) * Pdim + bp * 128;
#pragma unroll
            for (int nf = 0; nf < 4; nf++) {
                const int pl = wn * 32 + nf * 8 + tg * 2;
                float u0 = u_s[pl * 132 + nl];
                float u1 = u_s[(pl + 1) * 132 + nl];
                float2 z;
                z.x = ((float)accH[mf][nf][r2 * 2 + 0]
                       + (float)accL[mf][nf][r2 * 2 + 0] * 0.0078125f) * sc
                      - __logf(-__logf(u0));
                z.y = ((float)accH[mf][nf][r2 * 2 + 1]
                       + (float)accL[mf][nf][r2 * 2 + 1] * 0.0078125f) * sc
                      - __logf(-__logf(u1));
                *(float2*)&g_ZT[rowbase + pl] = z;
            }
        }
    }
}

// ---------------------------------------------------------------------------
// K2: warp-per-(b,n) softmax over p; emit int8 limbs of exp (scale 1/127) + 1/sum
// ---------------------------------------------------------------------------
__global__ __launch_bounds__(256) void k2_softmax() {
    int wid = threadIdx.x >> 5, lane = threadIdx.x & 31;
    int n = blockIdx.x * 8 + wid, b = blockIdx.y;
    size_t rb = ((size_t)b * Ndim + n) * Pdim;
    const float4* row = (const float4*)(g_ZT + rb);
    float m = -3.4e38f;
#pragma unroll
    for (int i = 0; i < 16; i++) {
        float4 v = row[lane + 32 * i];
        m = fmaxf(m, fmaxf(fmaxf(v.x, v.y), fmaxf(v.z, v.w)));
    }
#pragma unroll
    for (int o = 16; o > 0; o >>= 1) m = fmaxf(m, __shfl_xor_sync(0xFFFFFFFFu, m, o));
    float s = 0.f;
#pragma unroll 4
    for (int i = 0; i < 16; i++) {
        int i4 = lane + 32 * i;
        float4 v = row[i4];
        float e0 = __expf(v.x - m), e1 = __expf(v.y - m);
        float e2 = __expf(v.z - m), e3 = __expf(v.w - m);
        s += (e0 + e1) + (e2 + e3);
        float q0 = e0 * 127.f, q1 = e1 * 127.f, q2 = e2 * 127.f, q3 = e3 * 127.f;
        int i0 = __float2int_rn(q0), i1 = __float2int_rn(q1);
        int i2 = __float2int_rn(q2), i3 = __float2int_rn(q3);
        char4 c0 = {(char)i0, (char)i1, (char)i2, (char)i3};
        char4 c1 = {(char)__float2int_rn((q0 - i0) * 128.f),
                    (char)__float2int_rn((q1 - i1) * 128.f),
                    (char)__float2int_rn((q2 - i2) * 128.f),
                    (char)__float2int_rn((q3 - i3) * 128.f)};
        *(char4*)(g_a0 + rb + i4 * 4) = c0;
        *(char4*)(g_a1 + rb + i4 * 4) = c1;
    }
#pragma unroll
    for (int o = 16; o > 0; o >>= 1) s += __shfl_xor_sync(0xFFFFFFFFu, s, o);
    if (lane == 0) g_inv[(size_t)b * Ndim + n] = 1.0f / s;
}

// ---------------------------------------------------------------------------
// K3: out[b][n][d] = inv[b][n]/127^2 * (accH + accL/128).  M=n, N=d, K=p.
// ---------------------------------------------------------------------------
__global__ __launch_bounds__(256) void k3_combine(float* __restrict__ out) {
    extern __shared__ char smem[];
    const uint32_t smem_b = smem_u32_of(smem);
    const int tid = threadIdx.x, lane = tid & 31, wid = tid >> 5;
    const int wm = wid & 1, wn = wid >> 1;
    const int dt = blockIdx.x, nt = blockIdx.y, b = blockIdx.z;

    int accH[4][4][4], accL[4][4][4];
    gemm_mainloop(g_a0 + ((size_t)b * Ndim + nt * 128) * Pdim,
                  g_a1 + ((size_t)b * Ndim + nt * 128) * Pdim,
                  g_pt0 + (size_t)(dt * 128) * Pdim,
                  g_pt1 + (size_t)(dt * 128) * Pdim,
                  (size_t)Pdim, Pdim / KTB, smem_b, tid, accH, accL);

    const int gID = lane >> 2, tg = lane & 3;
    const float kq = 1.f / (127.f * 127.f);
#pragma unroll
    for (int mf = 0; mf < 4; mf++) {
#pragma unroll
        for (int r2 = 0; r2 < 2; r2++) {
            const int nl = wm * 64 + mf * 16 + gID + r2 * 8;
            const int n_g = nt * 128 + nl;
            const float sc = g_inv[(size_t)b * Ndim + n_g] * kq;
            const size_t rowbase = ((size_t)b * Ndim + n_g) * Ddim + dt * 128;
#pragma unroll
            for (int nf = 0; nf < 4; nf++) {
                const int dl = wn * 32 + nf * 8 + tg * 2;
                float2 o;
                o.x = ((float)accH[mf][nf][r2 * 2 + 0]
                       + (float)accL[mf][nf][r2 * 2 + 0] * 0.0078125f) * sc;
                o.y = ((float)accH[mf][nf][r2 * 2 + 1]
                       + (float)accL[mf][nf][r2 * 2 + 1] * 0.0078125f) * sc;
                *(float2*)&out[rowbase + dl] = o;
            }
        }
    }
}

// ---------------------------------------------------------------------------
extern "C" void kernel_launch(void* const* d_in, const int* in_sizes, int n_in,
                              void* d_out, int out_size)
{
    (void)in_sizes; (void)n_in; (void)out_size;
    const float* x     = (const float*)d_in[0];  // [B, N, D]
    const float* u     = (const float*)d_in[1];  // [B, P, N]
    const float* proto = (const float*)d_in[2];  // [P, D]
    float* out = (float*)d_out;                  // [B, N, D]

    cudaFuncSetAttribute(k1_logits, cudaFuncAttributeMaxDynamicSharedMemorySize, DYN_SMEM);
    cudaFuncSetAttribute(k3_combine, cudaFuncAttributeMaxDynamicSharedMemorySize, DYN_SMEM);

    quant_x<<<(Bdim * Ndim) / 8, 256>>>(x);
    quant_p<<<(Pdim * Ddim) / 256, 256>>>(proto);

    dim3 g1(Ndim / 128, Pdim / 128, Bdim);
    k1_logits<<<g1, 256, DYN_SMEM>>>(u);

    dim3 g2(Ndim / 8, Bdim);
    k2_softmax<<<g2, 256>>>();

    dim3 g3(Ddim / 128, Ndim / 128, Bdim);
    k3_combine<<<g3, 256, DYN_SMEM>>>(out);
}

// round 5
// speedup vs baseline: 2.6013x; 2.6013x over previous
#include <cuda_runtime.h>
#include <cuda_bf16.h>
#include <cstdint>

#define Bdim 16
#define Ndim 2048
#define Ddim 1024
#define Pdim 2048

// ---------------- device scratch (static; allocation-free rule) ----------------
__device__ __align__(256) __nv_bfloat16 g_xh[(size_t)Bdim * Ndim * Ddim];   // x hi  [b][n][d]
__device__ __align__(256) __nv_bfloat16 g_xl[(size_t)Bdim * Ndim * Ddim];   // x lo
__device__ __align__(256) __nv_bfloat16 g_ph[(size_t)Pdim * Ddim];          // proto hi [p][d]
__device__ __align__(256) __nv_bfloat16 g_pl[(size_t)Pdim * Ddim];
__device__ __align__(256) __nv_bfloat16 g_pth[(size_t)Ddim * Pdim];         // protoT hi [d][p]
__device__ __align__(256) __nv_bfloat16 g_ptl[(size_t)Ddim * Pdim];
__device__ __align__(256) float         g_ZT[(size_t)Bdim * Ndim * Pdim];   // Z^T [b][n][p]
__device__ __align__(256) __nv_bfloat16 g_aTh[(size_t)Bdim * Ndim * Pdim];  // exp hi [b][n][p]
__device__ __align__(256) __nv_bfloat16 g_aTl[(size_t)Bdim * Ndim * Pdim];  // exp lo
__device__ __align__(256) float         g_inv[(size_t)Bdim * Ndim];

// ---------------- baseline-PTX helpers (sm_80-class only; no 'a' features) -----
__device__ __forceinline__ uint32_t smem_u32_of(const void* p) {
    uint32_t a;
    asm("{ .reg .u64 t; cvta.to.shared.u64 t, %1; cvt.u32.u64 %0, t; }" : "=r"(a) : "l"(p));
    return a;
}
__device__ __forceinline__ void cpasync16(uint32_t s, const void* g) {
    asm volatile("cp.async.cg.shared.global [%0], [%1], 16;" :: "r"(s), "l"(g));
}
#define CP_COMMIT() asm volatile("cp.async.commit_group;")
#define CP_WAIT(n)  asm volatile("cp.async.wait_group %0;" :: "n"(n))

__device__ __forceinline__ void ldsm4(uint32_t* r, uint32_t addr) {
    asm volatile("ldmatrix.sync.aligned.m8n8.x4.shared.b16 {%0,%1,%2,%3}, [%4];"
                 : "=r"(r[0]), "=r"(r[1]), "=r"(r[2]), "=r"(r[3]) : "r"(addr));
}
__device__ __forceinline__ void mma16816(float* c, const uint32_t* a, const uint32_t* b) {
    asm volatile("mma.sync.aligned.m16n8k16.row.col.f32.bf16.bf16.f32 "
                 "{%0,%1,%2,%3}, {%4,%5,%6,%7}, {%8,%9}, {%0,%1,%2,%3};"
                 : "+f"(c[0]), "+f"(c[1]), "+f"(c[2]), "+f"(c[3])
                 : "r"(a[0]), "r"(a[1]), "r"(a[2]), "r"(a[3]), "r"(b[0]), "r"(b[1]));
}

// ---------------- tiling constants ----------------
static constexpr int KT = 32;                 // bf16 k per stage
static constexpr int ROWB = 80;               // padded smem row bytes (64 data + 16 pad)
static constexpr int TILE_B = 128 * ROWB;     // 10240 per operand tile
static constexpr int STAGE_B = 4 * TILE_B;    // Ah Al Bh Bl = 40960
static constexpr int DYN_SMEM = 2 * STAGE_B;  // 81920 -> 2 CTAs/SM

// load one stage (4 tiles x 128 rows x 64B), 8 cp.async per thread
__device__ __forceinline__ void load_stage(
    const __nv_bfloat16* gAh, const __nv_bfloat16* gAl,
    const __nv_bfloat16* gBh, const __nv_bfloat16* gBl,
    size_t Ks, int k0, uint32_t sbase, int tid)
{
    const __nv_bfloat16* G[4] = {gAh, gAl, gBh, gBl};
    const int q = tid & 3;            // 16B chunk within 64B row
    const int r0 = tid >> 2;          // 0..63
#pragma unroll
    for (int i = 0; i < 8; i++) {
        const int tile = i >> 1;
        const int r = (i & 1) * 64 + r0;
        cpasync16(sbase + tile * TILE_B + r * ROWB + q * 16,
                  G[tile] + (size_t)r * Ks + k0 + q * 8);
    }
}

// compute one k32 stage: 2 k-steps x (4 m-frags x 4 n-frags x 3 split-MMAs)
__device__ __forceinline__ void compute_stage(
    uint32_t sbase, int wm, int wn, uint32_t aoff, uint32_t boff,
    float acc[4][4][4])
{
    const uint32_t sAh = sbase;
    const uint32_t sAl = sbase + TILE_B;
    const uint32_t sBh = sbase + 2 * TILE_B;
    const uint32_t sBl = sbase + 3 * TILE_B;
#pragma unroll
    for (int ks = 0; ks < 2; ks++) {
        const uint32_t kb = ks * 32;   // 16 bf16 = 32 bytes
        uint32_t bh[8], bl[8];
#pragma unroll
        for (int f = 0; f < 2; f++) {
            uint32_t off = (wn * 32 + f * 16) * ROWB + kb + boff;
            ldsm4(bh + f * 4, sBh + off);
            ldsm4(bl + f * 4, sBl + off);
        }
#pragma unroll
        for (int mf = 0; mf < 4; mf++) {
            uint32_t off = (wm * 64 + mf * 16) * ROWB + kb + aoff;
            uint32_t ah[4], al[4];
            ldsm4(ah, sAh + off);
            ldsm4(al, sAl + off);
#pragma unroll
            for (int nf = 0; nf < 4; nf++) {
                mma16816(acc[mf][nf], ah, bh + nf * 2);
                mma16816(acc[mf][nf], ah, bl + nf * 2);
                mma16816(acc[mf][nf], al, bh + nf * 2);
            }
        }
    }
}

__device__ __forceinline__ void gemm_mainloop(
    const __nv_bfloat16* gAh, const __nv_bfloat16* gAl,
    const __nv_bfloat16* gBh, const __nv_bfloat16* gBl,
    size_t Ks, int T, uint32_t smem_b, int tid, float acc[4][4][4])
{
    const int lane = tid & 31, wid = tid >> 5;
    const int wm = wid & 1, wn = wid >> 1;
    const uint32_t aoff = (uint32_t)((lane & 15) * ROWB + ((lane & 16) ? 16 : 0));
    const uint32_t boff = (uint32_t)(((lane & 7) + ((lane & 16) ? 8 : 0)) * ROWB
                                     + ((lane & 8) ? 16 : 0));
#pragma unroll
    for (int mf = 0; mf < 4; mf++)
#pragma unroll
        for (int nf = 0; nf < 4; nf++)
#pragma unroll
            for (int e = 0; e < 4; e++) acc[mf][nf][e] = 0.f;

    load_stage(gAh, gAl, gBh, gBl, Ks, 0, smem_b, tid);
    CP_COMMIT();
    load_stage(gAh, gAl, gBh, gBl, Ks, KT, smem_b + STAGE_B, tid);
    CP_COMMIT();

    for (int t = 0; t < T; t++) {
        if (t == T - 1) { CP_WAIT(0); } else { CP_WAIT(1); }
        __syncthreads();
        compute_stage(smem_b + (t & 1) * STAGE_B, wm, wn, aoff, boff, acc);
        __syncthreads();
        if (t + 2 < T) {
            load_stage(gAh, gAl, gBh, gBl, Ks, (t + 2) * KT, smem_b + (t & 1) * STAGE_B, tid);
            CP_COMMIT();
        }
    }
}

// ---------------------------------------------------------------------------
// conv kernels: fp32 -> bf16 hi/lo splits
// ---------------------------------------------------------------------------
__global__ __launch_bounds__(256) void conv_x(const float* __restrict__ x) {
    size_t i = ((size_t)blockIdx.x * 256 + threadIdx.x) * 4;
    float4 v = *(const float4*)(x + i);
    __nv_bfloat16 h0 = __float2bfloat16(v.x), h1 = __float2bfloat16(v.y);
    __nv_bfloat16 h2 = __float2bfloat16(v.z), h3 = __float2bfloat16(v.w);
    __nv_bfloat162* oh = (__nv_bfloat162*)(g_xh + i);
    __nv_bfloat162* ol = (__nv_bfloat162*)(g_xl + i);
    oh[0] = __nv_bfloat162{h0, h1}; oh[1] = __nv_bfloat162{h2, h3};
    ol[0] = __nv_bfloat162{__float2bfloat16(v.x - __bfloat162float(h0)),
                           __float2bfloat16(v.y - __bfloat162float(h1))};
    ol[1] = __nv_bfloat162{__float2bfloat16(v.z - __bfloat162float(h2)),
                           __float2bfloat16(v.w - __bfloat162float(h3))};
}
__global__ __launch_bounds__(256) void conv_p(const float* __restrict__ proto) {
    int idx = blockIdx.x * 256 + threadIdx.x;
    int p = idx / Ddim, d = idx % Ddim;
    float v = proto[idx];
    __nv_bfloat16 h = __float2bfloat16(v);
    __nv_bfloat16 l = __float2bfloat16(v - __bfloat162float(h));
    g_ph[idx] = h; g_pl[idx] = l;
    g_pth[(size_t)d * Pdim + p] = h; g_ptl[(size_t)d * Pdim + p] = l;
}

// ---------------------------------------------------------------------------
// K1: Z^T[b][n][p] = x.proto^T + gumbel.  M=n(128), N=p(128), K=d.
// ---------------------------------------------------------------------------
__global__ __launch_bounds__(256, 2) void k1_logits(const float* __restrict__ u) {
    extern __shared__ char smem[];
    const uint32_t smem_b = smem_u32_of(smem);
    const int tid = threadIdx.x, lane = tid & 31, wid = tid >> 5;
    const int wm = wid & 1, wn = wid >> 1;
    const int bn = blockIdx.x, bp = blockIdx.y, b = blockIdx.z;

    float acc[4][4][4];
    gemm_mainloop(g_xh + ((size_t)b * Ndim + bn * 128) * Ddim,
                  g_xl + ((size_t)b * Ndim + bn * 128) * Ddim,
                  g_ph + (size_t)(bp * 128) * Ddim,
                  g_pl + (size_t)(bp * 128) * Ddim,
                  (size_t)Ddim, Ddim / KT, smem_b, tid, acc);

    // stage u tile [p0..p0+127][n0..n0+127] into smem (stride 132 floats)
    __syncthreads();
    float* u_s = (float*)smem;
    const float* ug = u + ((size_t)b * Pdim + (size_t)bp * 128) * Ndim + bn * 128;
#pragma unroll
    for (int j = 0; j < 16; j++) {
        int idx = tid + j * 256;        // 0..4095 float4s
        int row = idx >> 5, c4 = idx & 31;
        float4 v = *(const float4*)(ug + (size_t)row * Ndim + c4 * 4);
        *(float4*)(u_s + row * 132 + c4 * 4) = v;
    }
    __syncthreads();

    const int gID = lane >> 2, tg = lane & 3;
#pragma unroll
    for (int mf = 0; mf < 4; mf++) {
#pragma unroll
        for (int r2 = 0; r2 < 2; r2++) {
            const int nl = wm * 64 + mf * 16 + gID + r2 * 8;
            const size_t rowbase = ((size_t)b * Ndim + bn * 128 + nl) * Pdim + bp * 128;
#pragma unroll
            for (int nf = 0; nf < 4; nf++) {
                const int pl = wn * 32 + nf * 8 + tg * 2;
                float u0 = u_s[pl * 132 + nl];
                float u1 = u_s[(pl + 1) * 132 + nl];
                float2 z;
                z.x = acc[mf][nf][r2 * 2 + 0] - __logf(-__logf(u0));
                z.y = acc[mf][nf][r2 * 2 + 1] - __logf(-__logf(u1));
                *(float2*)&g_ZT[rowbase + pl] = z;
            }
        }
    }
}

// ---------------------------------------------------------------------------
// K2: warp-per-(b,n) softmax over p; emit bf16 hi/lo of exp + 1/sum
// ---------------------------------------------------------------------------
__global__ __launch_bounds__(256) void k2_softmax() {
    int wid = threadIdx.x >> 5, lane = threadIdx.x & 31;
    int n = blockIdx.x * 8 + wid, b = blockIdx.y;
    size_t rb = ((size_t)b * Ndim + n) * Pdim;
    const float4* row = (const float4*)(g_ZT + rb);
    float m = -3.4e38f;
#pragma unroll
    for (int i = 0; i < 16; i++) {
        float4 v = row[lane + 32 * i];
        m = fmaxf(m, fmaxf(fmaxf(v.x, v.y), fmaxf(v.z, v.w)));
    }
#pragma unroll
    for (int o = 16; o > 0; o >>= 1) m = fmaxf(m, __shfl_xor_sync(0xFFFFFFFFu, m, o));
    float s = 0.f;
    __nv_bfloat162* oh = (__nv_bfloat162*)(g_aTh + rb);
    __nv_bfloat162* ol = (__nv_bfloat162*)(g_aTl + rb);
#pragma unroll 4
    for (int i = 0; i < 16; i++) {
        int i4 = lane + 32 * i;
        float4 v = row[i4];
        float e0 = __expf(v.x - m), e1 = __expf(v.y - m);
        float e2 = __expf(v.z - m), e3 = __expf(v.w - m);
        s += (e0 + e1) + (e2 + e3);
        __nv_bfloat16 h0 = __float2bfloat16(e0), h1 = __float2bfloat16(e1);
        __nv_bfloat16 h2 = __float2bfloat16(e2), h3 = __float2bfloat16(e3);
        oh[i4 * 2 + 0] = __nv_bfloat162{h0, h1};
        oh[i4 * 2 + 1] = __nv_bfloat162{h2, h3};
        ol[i4 * 2 + 0] = __nv_bfloat162{__float2bfloat16(e0 - __bfloat162float(h0)),
                                        __float2bfloat16(e1 - __bfloat162float(h1))};
        ol[i4 * 2 + 1] = __nv_bfloat162{__float2bfloat16(e2 - __bfloat162float(h2)),
                                        __float2bfloat16(e3 - __bfloat162float(h3))};
    }
#pragma unroll
    for (int o = 16; o > 0; o >>= 1) s += __shfl_xor_sync(0xFFFFFFFFu, s, o);
    if (lane == 0) g_inv[(size_t)b * Ndim + n] = 1.0f / s;
}

// ---------------------------------------------------------------------------
// K3: out[b][n][d] = inv[b][n] * sum_p a^T[n][p] protoT[d][p].  M=n, N=d, K=p.
// ---------------------------------------------------------------------------
__global__ __launch_bounds__(256, 2) void k3_combine(float* __restrict__ out) {
    extern __shared__ char smem[];
    const uint32_t smem_b = smem_u32_of(smem);
    const int tid = threadIdx.x, lane = tid & 31, wid = tid >> 5;
    const int wm = wid & 1, wn = wid >> 1;
    const int dt = blockIdx.x, nt = blockIdx.y, b = blockIdx.z;

    float acc[4][4][4];
    gemm_mainloop(g_aTh + ((size_t)b * Ndim + nt * 128) * Pdim,
                  g_aTl + ((size_t)b * Ndim + nt * 128) * Pdim,
                  g_pth + (size_t)(dt * 128) * Pdim,
                  g_ptl + (size_t)(dt * 128) * Pdim,
                  (size_t)Pdim, Pdim / KT, smem_b, tid, acc);

    const int gID = lane >> 2, tg = lane & 3;
#pragma unroll
    for (int mf = 0; mf < 4; mf++) {
#pragma unroll
        for (int r2 = 0; r2 < 2; r2++) {
            const int nl = wm * 64 + mf * 16 + gID + r2 * 8;
            const int n_g = nt * 128 + nl;
            const float sc = g_inv[(size_t)b * Ndim + n_g];
            const size_t rowbase = ((size_t)b * Ndim + n_g) * Ddim + dt * 128;
#pragma unroll
            for (int nf = 0; nf < 4; nf++) {
                const int dl = wn * 32 + nf * 8 + tg * 2;
                float2 o;
                o.x = acc[mf][nf][r2 * 2 + 0] * sc;
                o.y = acc[mf][nf][r2 * 2 + 1] * sc;
                *(float2*)&out[rowbase + dl] = o;
            }
        }
    }
}

// ---------------------------------------------------------------------------
extern "C" void kernel_launch(void* const* d_in, const int* in_sizes, int n_in,
                              void* d_out, int out_size)
{
    (void)in_sizes; (void)n_in; (void)out_size;
    const float* x     = (const float*)d_in[0];  // [B, N, D]
    const float* u     = (const float*)d_in[1];  // [B, P, N]
    const float* proto = (const float*)d_in[2];  // [P, D]
    float* out = (float*)d_out;                  // [B, N, D]

    cudaFuncSetAttribute(k1_logits, cudaFuncAttributeMaxDynamicSharedMemorySize, DYN_SMEM);
    cudaFuncSetAttribute(k3_combine, cudaFuncAttributeMaxDynamicSharedMemorySize, DYN_SMEM);

    conv_x<<<(int)(((size_t)Bdim * Ndim * Ddim) / 4 / 256), 256>>>(x);
    conv_p<<<(Pdim * Ddim) / 256, 256>>>(proto);

    dim3 g1(Ndim / 128, Pdim / 128, Bdim);
    k1_logits<<<g1, 256, DYN_SMEM>>>(u);

    dim3 g2(Ndim / 8, Bdim);
    k2_softmax<<<g2, 256>>>();

    dim3 g3(Ddim / 128, Ndim / 128, Bdim);
    k3_combine<<<g3, 256, DYN_SMEM>>>(out);
}

// round 6
// speedup vs baseline: 5.7003x; 2.1913x over previous
#include <cuda_runtime.h>
#include <cuda_fp16.h>
#include <cstdint>

#define Bdim 16
#define Ndim 2048
#define Ddim 1024
#define Pdim 2048

// ---------------- device scratch (static; allocation-free rule) ----------------
__device__ __align__(256) __half g_x[(size_t)Bdim * Ndim * Ddim];    // x fp16 [b][n][d]
__device__ __align__(256) __half g_p[(size_t)Pdim * Ddim];           // (proto-0.5) [p][d]
__device__ __align__(256) __half g_pt[(size_t)Ddim * Pdim];          // (proto-0.5)^T [d][p]
__device__ __align__(256) float  g_ZT[(size_t)Bdim * Ndim * Pdim];   // Z^T [b][n][p]
__device__ __align__(256) __half g_a[(size_t)Bdim * Ndim * Pdim];    // quantized exp [b][n][p]
__device__ __align__(256) float  g_rs[(size_t)Bdim * Ndim];          // 0.5 * row-sum of x
__device__ __align__(256) float  g_inv[(size_t)Bdim * Ndim];         // 1/sum(quantized exp)

// ---------------- baseline-PTX helpers (sm_80-class only) ----------------------
__device__ __forceinline__ uint32_t smem_u32_of(const void* p) {
    uint32_t a;
    asm("{ .reg .u64 t; cvta.to.shared.u64 t, %1; cvt.u32.u64 %0, t; }" : "=r"(a) : "l"(p));
    return a;
}
__device__ __forceinline__ void cpasync16(uint32_t s, const void* g) {
    asm volatile("cp.async.cg.shared.global [%0], [%1], 16;" :: "r"(s), "l"(g));
}
#define CP_COMMIT() asm volatile("cp.async.commit_group;")
#define CP_WAIT(n)  asm volatile("cp.async.wait_group %0;" :: "n"(n))

__device__ __forceinline__ void ldsm4(uint32_t* r, uint32_t addr) {
    asm volatile("ldmatrix.sync.aligned.m8n8.x4.shared.b16 {%0,%1,%2,%3}, [%4];"
                 : "=r"(r[0]), "=r"(r[1]), "=r"(r[2]), "=r"(r[3]) : "r"(addr));
}
__device__ __forceinline__ void mma16816(float* c, const uint32_t* a, const uint32_t* b) {
    asm volatile("mma.sync.aligned.m16n8k16.row.col.f32.f16.f16.f32 "
                 "{%0,%1,%2,%3}, {%4,%5,%6,%7}, {%8,%9}, {%0,%1,%2,%3};"
                 : "+f"(c[0]), "+f"(c[1]), "+f"(c[2]), "+f"(c[3])
                 : "r"(a[0]), "r"(a[1]), "r"(a[2]), "r"(a[3]), "r"(b[0]), "r"(b[1]));
}

// ---------------- tiling constants ----------------
static constexpr int KT = 32;                 // fp16 k per stage
static constexpr int ROWB = 80;               // padded smem row bytes (64 data + 16 pad)
static constexpr int TILE_B = 128 * ROWB;     // 10240 per operand tile
static constexpr int STAGE_B = 2 * TILE_B;    // A, B = 20480
static constexpr int DYN_SMEM_K3 = 2 * STAGE_B;       // 40960
static constexpr int DYN_SMEM_K1 = 128 * 132 * 4;     // 67584 (u-tile staging dominates)

// load one stage (2 tiles x 128 rows x 64B), 4 cp.async per thread
__device__ __forceinline__ void load_stage(
    const __half* gA, const __half* gB,
    size_t Ks, int k0, uint32_t sbase, int tid)
{
    const __half* G[2] = {gA, gB};
#pragma unroll
    for (int j = 0; j < 4; j++) {
        const int idx = tid + j * 256;        // 0..1023
        const int tile = idx >> 9;
        const int c = idx & 511;
        const int row = c >> 2, q = c & 3;
        cpasync16(sbase + tile * TILE_B + row * ROWB + q * 16,
                  G[tile] + (size_t)row * Ks + k0 + q * 8);
    }
}

// compute one k32 stage: 2 k-steps x (4 m-frags x 4 n-frags), single term
__device__ __forceinline__ void compute_stage(
    uint32_t sbase, int wm, int wn, uint32_t aoff, uint32_t boff,
    float acc[4][4][4])
{
    const uint32_t sA = sbase;
    const uint32_t sB = sbase + TILE_B;
#pragma unroll
    for (int ks = 0; ks < 2; ks++) {
        const uint32_t kb = ks * 32;   // 16 fp16 = 32 bytes
        uint32_t bf[8];
#pragma unroll
        for (int f = 0; f < 2; f++) {
            uint32_t off = (wn * 32 + f * 16) * ROWB + kb + boff;
            ldsm4(bf + f * 4, sB + off);
        }
#pragma unroll
        for (int mf = 0; mf < 4; mf++) {
            uint32_t off = (wm * 64 + mf * 16) * ROWB + kb + aoff;
            uint32_t af[4];
            ldsm4(af, sA + off);
#pragma unroll
            for (int nf = 0; nf < 4; nf++)
                mma16816(acc[mf][nf], af, bf + nf * 2);
        }
    }
}

__device__ __forceinline__ void gemm_mainloop(
    const __half* gA, const __half* gB,
    size_t Ks, int T, uint32_t smem_b, int tid, float acc[4][4][4])
{
    const int lane = tid & 31, wid = tid >> 5;
    const int wm = wid & 1, wn = wid >> 1;
    const uint32_t aoff = (uint32_t)((lane & 15) * ROWB + ((lane & 16) ? 16 : 0));
    const uint32_t boff = (uint32_t)(((lane & 7) + ((lane & 16) ? 8 : 0)) * ROWB
                                     + ((lane & 8) ? 16 : 0));
#pragma unroll
    for (int mf = 0; mf < 4; mf++)
#pragma unroll
        for (int nf = 0; nf < 4; nf++)
#pragma unroll
            for (int e = 0; e < 4; e++) acc[mf][nf][e] = 0.f;

    load_stage(gA, gB, Ks, 0, smem_b, tid);
    CP_COMMIT();
    load_stage(gA, gB, Ks, KT, smem_b + STAGE_B, tid);
    CP_COMMIT();

    for (int t = 0; t < T; t++) {
        if (t == T - 1) { CP_WAIT(0); } else { CP_WAIT(1); }
        __syncthreads();
        compute_stage(smem_b + (t & 1) * STAGE_B, wm, wn, aoff, boff, acc);
        __syncthreads();
        if (t + 2 < T) {
            load_stage(gA, gB, Ks, (t + 2) * KT, smem_b + (t & 1) * STAGE_B, tid);
            CP_COMMIT();
        }
    }
}

// ---------------------------------------------------------------------------
// quant_x: x -> fp16, plus 0.5*row-sum (exact fp32) for the centering correction
// one warp per (b,n) row
// ---------------------------------------------------------------------------
__global__ __launch_bounds__(256) void quant_x(const float* __restrict__ x) {
    const int w = blockIdx.x * 8 + (threadIdx.x >> 5);
    const int lane = threadIdx.x & 31;
    const float4* row = (const float4*)(x + (size_t)w * Ddim);
    float s = 0.f;
#pragma unroll
    for (int i = 0; i < 8; i++) {
        float4 v = row[lane + 32 * i];
        s += (v.x + v.y) + (v.z + v.w);
        __half2 h01 = __floats2half2_rn(v.x, v.y);
        __half2 h23 = __floats2half2_rn(v.z, v.w);
        __half2* o = (__half2*)(g_x + (size_t)w * Ddim + (lane + 32 * i) * 4);
        o[0] = h01; o[1] = h23;
    }
#pragma unroll
    for (int o = 16; o > 0; o >>= 1) s += __shfl_xor_sync(0xFFFFFFFFu, s, o);
    if (lane == 0) g_rs[w] = 0.5f * s;
}
// quant_p: (proto - 0.5) -> fp16, row-major and transposed
__global__ __launch_bounds__(256) void quant_p(const float* __restrict__ proto) {
    int idx = blockIdx.x * 256 + threadIdx.x;
    int p = idx / Ddim, d = idx % Ddim;
    __half h = __float2half_rn(proto[idx] - 0.5f);
    g_p[idx] = h;
    g_pt[(size_t)d * Pdim + p] = h;
}

// ---------------------------------------------------------------------------
// K1: Z^T[b][n][p] = x.(proto-0.5)^T + 0.5*rowsum(x) + gumbel.  M=n, N=p, K=d.
// ---------------------------------------------------------------------------
__global__ __launch_bounds__(256, 2) void k1_logits(const float* __restrict__ u) {
    extern __shared__ char smem[];
    const uint32_t smem_b = smem_u32_of(smem);
    const int tid = threadIdx.x, lane = tid & 31, wid = tid >> 5;
    const int wm = wid & 1, wn = wid >> 1;
    const int bn = blockIdx.x, bp = blockIdx.y, b = blockIdx.z;

    float acc[4][4][4];
    gemm_mainloop(g_x + ((size_t)b * Ndim + bn * 128) * Ddim,
                  g_p + (size_t)(bp * 128) * Ddim,
                  (size_t)Ddim, Ddim / KT, smem_b, tid, acc);

    // stage u tile [p0..p0+127][n0..n0+127] into smem (stride 132 floats)
    __syncthreads();
    float* u_s = (float*)smem;
    const float* ug = u + ((size_t)b * Pdim + (size_t)bp * 128) * Ndim + bn * 128;
#pragma unroll
    for (int j = 0; j < 16; j++) {
        int idx = tid + j * 256;
        int row = idx >> 5, c4 = idx & 31;
        float4 v = *(const float4*)(ug + (size_t)row * Ndim + c4 * 4);
        *(float4*)(u_s + row * 132 + c4 * 4) = v;
    }
    __syncthreads();

    const int gID = lane >> 2, tg = lane & 3;
#pragma unroll
    for (int mf = 0; mf < 4; mf++) {
#pragma unroll
        for (int r2 = 0; r2 < 2; r2++) {
            const int nl = wm * 64 + mf * 16 + gID + r2 * 8;
            const float rsv = g_rs[(size_t)b * Ndim + bn * 128 + nl];
            const size_t rowbase = ((size_t)b * Ndim + bn * 128 + nl) * Pdim + bp * 128;
#pragma unroll
            for (int nf = 0; nf < 4; nf++) {
                const int pl = wn * 32 + nf * 8 + tg * 2;
                float u0 = u_s[pl * 132 + nl];
                float u1 = u_s[(pl + 1) * 132 + nl];
                float2 z;
                z.x = acc[mf][nf][r2 * 2 + 0] + rsv - __logf(-__logf(u0));
                z.y = acc[mf][nf][r2 * 2 + 1] + rsv - __logf(-__logf(u1));
                *(float2*)&g_ZT[rowbase + pl] = z;
            }
        }
    }
}

// ---------------------------------------------------------------------------
// K2: warp-per-(b,n) softmax over p; emit fp16 exp, 1/sum over QUANTIZED values
// ---------------------------------------------------------------------------
__global__ __launch_bounds__(256) void k2_softmax() {
    int wid = threadIdx.x >> 5, lane = threadIdx.x & 31;
    int n = blockIdx.x * 8 + wid, b = blockIdx.y;
    size_t rb = ((size_t)b * Ndim + n) * Pdim;
    const float4* row = (const float4*)(g_ZT + rb);
    float m = -3.4e38f;
#pragma unroll
    for (int i = 0; i < 16; i++) {
        float4 v = row[lane + 32 * i];
        m = fmaxf(m, fmaxf(fmaxf(v.x, v.y), fmaxf(v.z, v.w)));
    }
#pragma unroll
    for (int o = 16; o > 0; o >>= 1) m = fmaxf(m, __shfl_xor_sync(0xFFFFFFFFu, m, o));
    float s = 0.f;
    __half2* oa = (__half2*)(g_a + rb);
#pragma unroll 4
    for (int i = 0; i < 16; i++) {
        int i4 = lane + 32 * i;
        float4 v = row[i4];
        __half2 h01 = __floats2half2_rn(__expf(v.x - m), __expf(v.y - m));
        __half2 h23 = __floats2half2_rn(__expf(v.z - m), __expf(v.w - m));
        // sum the QUANTIZED values so K3's normalization is exactly consistent
        float2 f01 = __half22float2(h01), f23 = __half22float2(h23);
        s += (f01.x + f01.y) + (f23.x + f23.y);
        oa[i4 * 2 + 0] = h01;
        oa[i4 * 2 + 1] = h23;
    }
#pragma unroll
    for (int o = 16; o > 0; o >>= 1) s += __shfl_xor_sync(0xFFFFFFFFu, s, o);
    if (lane == 0) g_inv[(size_t)b * Ndim + n] = 1.0f / s;
}

// ---------------------------------------------------------------------------
// K3: out[b][n][d] = inv[b][n] * sum_p a[n][p] (proto-0.5)^T[d][p] + 0.5
// M=n, N=d, K=p.
// ---------------------------------------------------------------------------
__global__ __launch_bounds__(256, 2) void k3_combine(float* __restrict__ out) {
    extern __shared__ char smem[];
    const uint32_t smem_b = smem_u32_of(smem);
    const int tid = threadIdx.x, lane = tid & 31, wid = tid >> 5;
    const int wm = wid & 1, wn = wid >> 1;
    const int dt = blockIdx.x, nt = blockIdx.y, b = blockIdx.z;

    float acc[4][4][4];
    gemm_mainloop(g_a + ((size_t)b * Ndim + nt * 128) * Pdim,
                  g_pt + (size_t)(dt * 128) * Pdim,
                  (size_t)Pdim, Pdim / KT, smem_b, tid, acc);

    const int gID = lane >> 2, tg = lane & 3;
#pragma unroll
    for (int mf = 0; mf < 4; mf++) {
#pragma unroll
        for (int r2 = 0; r2 < 2; r2++) {
            const int nl = wm * 64 + mf * 16 + gID + r2 * 8;
            const int n_g = nt * 128 + nl;
            const float sc = g_inv[(size_t)b * Ndim + n_g];
            const size_t rowbase = ((size_t)b * Ndim + n_g) * Ddim + dt * 128;
#pragma unroll
            for (int nf = 0; nf < 4; nf++) {
                const int dl = wn * 32 + nf * 8 + tg * 2;
                float2 o;
                o.x = acc[mf][nf][r2 * 2 + 0] * sc + 0.5f;
                o.y = acc[mf][nf][r2 * 2 + 1] * sc + 0.5f;
                *(float2*)&out[rowbase + dl] = o;
            }
        }
    }
}

// ---------------------------------------------------------------------------
extern "C" void kernel_launch(void* const* d_in, const int* in_sizes, int n_in,
                              void* d_out, int out_size)
{
    (void)in_sizes; (void)n_in; (void)out_size;
    const float* x     = (const float*)d_in[0];  // [B, N, D]
    const float* u     = (const float*)d_in[1];  // [B, P, N]
    const float* proto = (const float*)d_in[2];  // [P, D]
    float* out = (float*)d_out;                  // [B, N, D]

    cudaFuncSetAttribute(k1_logits, cudaFuncAttributeMaxDynamicSharedMemorySize, DYN_SMEM_K1);
    cudaFuncSetAttribute(k3_combine, cudaFuncAttributeMaxDynamicSharedMemorySize, DYN_SMEM_K3);

    quant_x<<<(Bdim * Ndim) / 8, 256>>>(x);
    quant_p<<<(Pdim * Ddim) / 256, 256>>>(proto);

    dim3 g1(Ndim / 128, Pdim / 128, Bdim);
    k1_logits<<<g1, 256, DYN_SMEM_K1>>>(u);

    dim3 g2(Ndim / 8, Bdim);
    k2_softmax<<<g2, 256>>>();

    dim3 g3(Ddim / 128, Ndim / 128, Bdim);
    k3_combine<<<g3, 256, DYN_SMEM_K3>>>(out);
}

// round 7
// speedup vs baseline: 6.3688x; 1.1173x over previous
#include <cuda_runtime.h>
#include <cuda_fp16.h>
#include <cstdint>

#define Bdim 16
#define Ndim 2048
#define Ddim 1024
#define Pdim 2048

// ---------------- device scratch (static; allocation-free rule) ----------------
__device__ __align__(256) __half g_x[(size_t)Bdim * Ndim * Ddim];    // x fp16 [b][n][d]
__device__ __align__(256) __half g_p[(size_t)Pdim * Ddim];           // (proto-0.5) [p][d]
__device__ __align__(256) __half g_pt[(size_t)Ddim * Pdim];          // (proto-0.5)^T [d][p]
__device__ __align__(256) float  g_ZT[(size_t)Bdim * Ndim * Pdim];   // Z^T [b][n][p]
__device__ __align__(256) __half g_a[(size_t)Bdim * Ndim * Pdim];    // quantized exp [b][n][p]
__device__ __align__(256) float  g_rs[(size_t)Bdim * Ndim];          // 0.5 * row-sum of x
__device__ __align__(256) float  g_inv[(size_t)Bdim * Ndim];         // 1/sum(quantized exp)

// ---------------- baseline-PTX helpers (sm_80-class only) ----------------------
__device__ __forceinline__ uint32_t smem_u32_of(const void* p) {
    uint32_t a;
    asm("{ .reg .u64 t; cvta.to.shared.u64 t, %1; cvt.u32.u64 %0, t; }" : "=r"(a) : "l"(p));
    return a;
}
__device__ __forceinline__ void cpasync16(uint32_t s, const void* g) {
    asm volatile("cp.async.cg.shared.global [%0], [%1], 16;" :: "r"(s), "l"(g));
}
#define CP_COMMIT() asm volatile("cp.async.commit_group;")
#define CP_WAIT(n)  asm volatile("cp.async.wait_group %0;" :: "n"(n))

__device__ __forceinline__ void ldsm4(uint32_t* r, uint32_t addr) {
    asm volatile("ldmatrix.sync.aligned.m8n8.x4.shared.b16 {%0,%1,%2,%3}, [%4];"
                 : "=r"(r[0]), "=r"(r[1]), "=r"(r[2]), "=r"(r[3]) : "r"(addr));
}
__device__ __forceinline__ void mma16816(float* c, const uint32_t* a, const uint32_t* b) {
    asm volatile("mma.sync.aligned.m16n8k16.row.col.f32.f16.f16.f32 "
                 "{%0,%1,%2,%3}, {%4,%5,%6,%7}, {%8,%9}, {%0,%1,%2,%3};"
                 : "+f"(c[0]), "+f"(c[1]), "+f"(c[2]), "+f"(c[3])
                 : "r"(a[0]), "r"(a[1]), "r"(a[2]), "r"(a[3]), "r"(b[0]), "r"(b[1]));
}

// ---------------- tiling constants ----------------
static constexpr int KT = 64;                 // fp16 k per stage (128 data bytes/row)
static constexpr int ROWB = 144;              // padded smem row bytes (128 + 16)
static constexpr int TILE_B = 128 * ROWB;     // 18432 per operand tile
static constexpr int STAGE_B = 2 * TILE_B;    // A, B = 36864
static constexpr int NSTG = 3;                // circular pipeline depth
static constexpr int DYN_SMEM = NSTG * STAGE_B;       // 110592 (k1 u-tile 67584 fits)

// load one stage (2 tiles x 128 rows x 128B), 8 cp.async per thread
__device__ __forceinline__ void load_stage(
    const __half* gA, const __half* gB,
    size_t Ks, int k0, uint32_t sbase, int tid)
{
    const __half* G[2] = {gA, gB};
#pragma unroll
    for (int j = 0; j < 8; j++) {
        const int idx = tid + j * 256;        // 0..2047
        const int tile = idx >> 10;
        const int c = idx & 1023;
        const int row = c >> 3, q = c & 7;
        cpasync16(sbase + tile * TILE_B + row * ROWB + q * 16,
                  G[tile] + (size_t)row * Ks + k0 + q * 8);
    }
}

// compute one k64 stage: 4 k16-steps x (4 m-frags x 4 n-frags)
__device__ __forceinline__ void compute_stage(
    uint32_t sbase, int wm, int wn, uint32_t aoff, uint32_t boff,
    float acc[4][4][4])
{
    const uint32_t sA = sbase;
    const uint32_t sB = sbase + TILE_B;
#pragma unroll
    for (int ks = 0; ks < 4; ks++) {
        const uint32_t kb = ks * 32;   // 16 fp16 = 32 bytes
        uint32_t bf[8];
#pragma unroll
        for (int f = 0; f < 2; f++) {
            uint32_t off = (wn * 32 + f * 16) * ROWB + kb + boff;
            ldsm4(bf + f * 4, sB + off);
        }
#pragma unroll
        for (int mf = 0; mf < 4; mf++) {
            uint32_t off = (wm * 64 + mf * 16) * ROWB + kb + aoff;
            uint32_t af[4];
            ldsm4(af, sA + off);
#pragma unroll
            for (int nf = 0; nf < 4; nf++)
                mma16816(acc[mf][nf], af, bf + nf * 2);
        }
    }
}

// 3-stage circular pipeline, one __syncthreads per stage
__device__ __forceinline__ void gemm_mainloop(
    const __half* gA, const __half* gB,
    size_t Ks, int T, uint32_t smem_b, int tid, float acc[4][4][4])
{
    const int lane = tid & 31, wid = tid >> 5;
    const int wm = wid & 1, wn = wid >> 1;
    const uint32_t aoff = (uint32_t)((lane & 15) * ROWB + ((lane & 16) ? 16 : 0));
    const uint32_t boff = (uint32_t)(((lane & 7) + ((lane & 16) ? 8 : 0)) * ROWB
                                     + ((lane & 8) ? 16 : 0));
#pragma unroll
    for (int mf = 0; mf < 4; mf++)
#pragma unroll
        for (int nf = 0; nf < 4; nf++)
#pragma unroll
            for (int e = 0; e < 4; e++) acc[mf][nf][e] = 0.f;

    load_stage(gA, gB, Ks, 0, smem_b, tid);
    CP_COMMIT();
    load_stage(gA, gB, Ks, KT, smem_b + STAGE_B, tid);
    CP_COMMIT();

    int s_cur = 0, s_nxt = 2;   // buffer indices mod 3
    for (int t = 0; t < T; t++) {
        if (t == T - 1) { CP_WAIT(0); } else { CP_WAIT(1); }
        __syncthreads();   // all warps done with buffer s_nxt's previous contents
        if (t + 2 < T) {
            load_stage(gA, gB, Ks, (t + 2) * KT, smem_b + s_nxt * STAGE_B, tid);
            CP_COMMIT();
        }
        compute_stage(smem_b + s_cur * STAGE_B, wm, wn, aoff, boff, acc);
        s_cur = (s_cur == 2) ? 0 : s_cur + 1;
        s_nxt = (s_nxt == 2) ? 0 : s_nxt + 1;
    }
}

// ---------------------------------------------------------------------------
// quant_x: x -> fp16, plus 0.5*row-sum (exact fp32) for the centering correction
// ---------------------------------------------------------------------------
__global__ __launch_bounds__(256) void quant_x(const float* __restrict__ x) {
    const int w = blockIdx.x * 8 + (threadIdx.x >> 5);
    const int lane = threadIdx.x & 31;
    const float4* row = (const float4*)(x + (size_t)w * Ddim);
    float s = 0.f;
#pragma unroll
    for (int i = 0; i < 8; i++) {
        float4 v = row[lane + 32 * i];
        s += (v.x + v.y) + (v.z + v.w);
        __half2 h01 = __floats2half2_rn(v.x, v.y);
        __half2 h23 = __floats2half2_rn(v.z, v.w);
        __half2* o = (__half2*)(g_x + (size_t)w * Ddim + (lane + 32 * i) * 4);
        o[0] = h01; o[1] = h23;
    }
#pragma unroll
    for (int o = 16; o > 0; o >>= 1) s += __shfl_xor_sync(0xFFFFFFFFu, s, o);
    if (lane == 0) g_rs[w] = 0.5f * s;
}
// quant_p: (proto - 0.5) -> fp16, row-major and transposed
__global__ __launch_bounds__(256) void quant_p(const float* __restrict__ proto) {
    int idx = blockIdx.x * 256 + threadIdx.x;
    int p = idx / Ddim, d = idx % Ddim;
    __half h = __float2half_rn(proto[idx] - 0.5f);
    g_p[idx] = h;
    g_pt[(size_t)d * Pdim + p] = h;
}

// ---------------------------------------------------------------------------
// K1: Z^T[b][n][p] = x.(proto-0.5)^T + 0.5*rowsum(x) + gumbel.  M=n, N=p, K=d.
// ---------------------------------------------------------------------------
__global__ __launch_bounds__(256, 2) void k1_logits(const float* __restrict__ u) {
    extern __shared__ char smem[];
    const uint32_t smem_b = smem_u32_of(smem);
    const int tid = threadIdx.x, lane = tid & 31, wid = tid >> 5;
    const int wm = wid & 1, wn = wid >> 1;
    const int bn = blockIdx.x, bp = blockIdx.y, b = blockIdx.z;

    float acc[4][4][4];
    gemm_mainloop(g_x + ((size_t)b * Ndim + bn * 128) * Ddim,
                  g_p + (size_t)(bp * 128) * Ddim,
                  (size_t)Ddim, Ddim / KT, smem_b, tid, acc);

    // stage u tile [p0..p0+127][n0..n0+127] into smem (stride 132 floats)
    __syncthreads();
    float* u_s = (float*)smem;
    const float* ug = u + ((size_t)b * Pdim + (size_t)bp * 128) * Ndim + bn * 128;
#pragma unroll
    for (int j = 0; j < 16; j++) {
        int idx = tid + j * 256;
        int row = idx >> 5, c4 = idx & 31;
        float4 v = *(const float4*)(ug + (size_t)row * Ndim + c4 * 4);
        *(float4*)(u_s + row * 132 + c4 * 4) = v;
    }
    __syncthreads();

    const int gID = lane >> 2, tg = lane & 3;
#pragma unroll
    for (int mf = 0; mf < 4; mf++) {
#pragma unroll
        for (int r2 = 0; r2 < 2; r2++) {
            const int nl = wm * 64 + mf * 16 + gID + r2 * 8;
            const float rsv = g_rs[(size_t)b * Ndim + bn * 128 + nl];
            const size_t rowbase = ((size_t)b * Ndim + bn * 128 + nl) * Pdim + bp * 128;
#pragma unroll
            for (int nf = 0; nf < 4; nf++) {
                const int pl = wn * 32 + nf * 8 + tg * 2;
                float u0 = u_s[pl * 132 + nl];
                float u1 = u_s[(pl + 1) * 132 + nl];
                float2 z;
                z.x = acc[mf][nf][r2 * 2 + 0] + rsv - __logf(-__logf(u0));
                z.y = acc[mf][nf][r2 * 2 + 1] + rsv - __logf(-__logf(u1));
                *(float2*)&g_ZT[rowbase + pl] = z;
            }
        }
    }
}

// ---------------------------------------------------------------------------
// K2: warp-per-(b,n) softmax over p; emit fp16 exp, 1/sum over QUANTIZED values
// ---------------------------------------------------------------------------
__global__ __launch_bounds__(256) void k2_softmax() {
    int wid = threadIdx.x >> 5, lane = threadIdx.x & 31;
    int n = blockIdx.x * 8 + wid, b = blockIdx.y;
    size_t rb = ((size_t)b * Ndim + n) * Pdim;
    const float4* row = (const float4*)(g_ZT + rb);
    float m = -3.4e38f;
#pragma unroll
    for (int i = 0; i < 16; i++) {
        float4 v = row[lane + 32 * i];
        m = fmaxf(m, fmaxf(fmaxf(v.x, v.y), fmaxf(v.z, v.w)));
    }
#pragma unroll
    for (int o = 16; o > 0; o >>= 1) m = fmaxf(m, __shfl_xor_sync(0xFFFFFFFFu, m, o));
    float s = 0.f;
    __half2* oa = (__half2*)(g_a + rb);
#pragma unroll 4
    for (int i = 0; i < 16; i++) {
        int i4 = lane + 32 * i;
        float4 v = row[i4];
        __half2 h01 = __floats2half2_rn(__expf(v.x - m), __expf(v.y - m));
        __half2 h23 = __floats2half2_rn(__expf(v.z - m), __expf(v.w - m));
        float2 f01 = __half22float2(h01), f23 = __half22float2(h23);
        s += (f01.x + f01.y) + (f23.x + f23.y);
        oa[i4 * 2 + 0] = h01;
        oa[i4 * 2 + 1] = h23;
    }
#pragma unroll
    for (int o = 16; o > 0; o >>= 1) s += __shfl_xor_sync(0xFFFFFFFFu, s, o);
    if (lane == 0) g_inv[(size_t)b * Ndim + n] = 1.0f / s;
}

// ---------------------------------------------------------------------------
// K3: out[b][n][d] = inv[b][n] * sum_p a[n][p] (proto-0.5)^T[d][p] + 0.5
// ---------------------------------------------------------------------------
__global__ __launch_bounds__(256, 2) void k3_combine(float* __restrict__ out) {
    extern __shared__ char smem[];
    const uint32_t smem_b = smem_u32_of(smem);
    const int tid = threadIdx.x, lane = tid & 31, wid = tid >> 5;
    const int wm = wid & 1, wn = wid >> 1;
    const int dt = blockIdx.x, nt = blockIdx.y, b = blockIdx.z;

    float acc[4][4][4];
    gemm_mainloop(g_a + ((size_t)b * Ndim + nt * 128) * Pdim,
                  g_pt + (size_t)(dt * 128) * Pdim,
                  (size_t)Pdim, Pdim / KT, smem_b, tid, acc);

    const int gID = lane >> 2, tg = lane & 3;
#pragma unroll
    for (int mf = 0; mf < 4; mf++) {
#pragma unroll
        for (int r2 = 0; r2 < 2; r2++) {
            const int nl = wm * 64 + mf * 16 + gID + r2 * 8;
            const int n_g = nt * 128 + nl;
            const float sc = g_inv[(size_t)b * Ndim + n_g];
            const size_t rowbase = ((size_t)b * Ndim + n_g) * Ddim + dt * 128;
#pragma unroll
            for (int nf = 0; nf < 4; nf++) {
                const int dl = wn * 32 + nf * 8 + tg * 2;
                float2 o;
                o.x = acc[mf][nf][r2 * 2 + 0] * sc + 0.5f;
                o.y = acc[mf][nf][r2 * 2 + 1] * sc + 0.5f;
                *(float2*)&out[rowbase + dl] = o;
            }
        }
    }
}

// ---------------------------------------------------------------------------
extern "C" void kernel_launch(void* const* d_in, const int* in_sizes, int n_in,
                              void* d_out, int out_size)
{
    (void)in_sizes; (void)n_in; (void)out_size;
    const float* x     = (const float*)d_in[0];  // [B, N, D]
    const float* u     = (const float*)d_in[1];  // [B, P, N]
    const float* proto = (const float*)d_in[2];  // [P, D]
    float* out = (float*)d_out;                  // [B, N, D]

    cudaFuncSetAttribute(k1_logits, cudaFuncAttributeMaxDynamicSharedMemorySize, DYN_SMEM);
    cudaFuncSetAttribute(k3_combine, cudaFuncAttributeMaxDynamicSharedMemorySize, DYN_SMEM);

    quant_x<<<(Bdim * Ndim) / 8, 256>>>(x);
    quant_p<<<(Pdim * Ddim) / 256, 256>>>(proto);

    dim3 g1(Ndim / 128, Pdim / 128, Bdim);
    k1_logits<<<g1, 256, DYN_SMEM>>>(u);

    dim3 g2(Ndim / 8, Bdim);
    k2_softmax<<<g2, 256>>>();

    dim3 g3(Ddim / 128, Ndim / 128, Bdim);
    k3_combine<<<g3, 256, DYN_SMEM>>>(out);
}